// round 11
// baseline (speedup 1.0000x reference)
#include <cuda_runtime.h>
#include <math.h>
#include <stdint.h>

// Problem constants
#define BB   128
#define TT   512
#define INDIM 128
#define HH   1024
#define G3   (3*HH)
#define PRED 96
#define MROWS (TT*BB)

#define NCOLB 64          // H/16 col blocks
#define NROWB 2           // B/64 row groups

// ---------------------------------------------------------------------------
// Scratch
// ---------------------------------------------------------------------------
__device__ float g_XT[(size_t)TT * BB * INDIM];
__device__ float g_XI[(size_t)TT * BB * G3];
__device__ float g_HA[(size_t)TT * BB * HH];
__device__ float g_HB[(size_t)TT * BB * HH];
__device__ uint32_t g_WIH[3][(size_t)G3 * HH];   // tf32 std layout (layer 0 uses G3*INDIM)
// fragment-permuted W_hh: [cb:64][ww:2][g:3][kf:128][lane:32] uint2
__device__ uint2 g_WHHP[3][(size_t)64 * 2 * 3 * 128 * 32];
// fragment-permuted h, ping-pong: [par:2][rg:2][kf:128][mq:4][lane:32] uint4
__device__ uint4 g_HP[2][32768];

__device__ unsigned g_cnt[NROWB];
__device__ unsigned g_gen[NROWB];

// ---------------------------------------------------------------------------
// PTX helpers
// ---------------------------------------------------------------------------
__device__ __forceinline__ void mma_tf32(float c[4], const uint32_t a[4], const uint32_t b[2]) {
    asm volatile(
        "mma.sync.aligned.m16n8k8.row.col.f32.tf32.tf32.f32 "
        "{%0,%1,%2,%3}, {%4,%5,%6,%7}, {%8,%9}, {%0,%1,%2,%3};\n"
        : "+f"(c[0]), "+f"(c[1]), "+f"(c[2]), "+f"(c[3])
        : "r"(a[0]), "r"(a[1]), "r"(a[2]), "r"(a[3]), "r"(b[0]), "r"(b[1]));
}
__device__ __forceinline__ uint32_t f2tf32(uint32_t x) {
    uint32_t y;
    asm volatile("cvt.rna.tf32.f32 %0, %1;" : "=r"(y) : "r"(x));
    return y;
}

// ---------------------------------------------------------------------------
// transpose x [B,T,IN] -> [T,B,IN]
// ---------------------------------------------------------------------------
__global__ __launch_bounds__(256) void transpose_x(const float* __restrict__ x,
                                                   float* __restrict__ xt) {
    int idx = blockIdx.x * blockDim.x + threadIdx.x;
    if (idx >= TT * BB * INDIM) return;
    int i = idx % INDIM;
    int r = idx / INDIM;
    int b = r % BB;
    int t = r / BB;
    xt[idx] = x[((size_t)b * TT + t) * INDIM + i];
}

// ---------------------------------------------------------------------------
// prep: (a) round w_ih to tf32; (b) fragment-permuted tf32 W_hh
// ---------------------------------------------------------------------------
#define WIH_F4_0 (G3 * INDIM / 4)            // 98304
#define WIH_F4_1 (G3 * HH / 4)               // 786432
#define PREP_WIH (WIH_F4_0 + 2 * WIH_F4_1)   // 1671168
#define WHHP_L   (64 * 2 * 3 * 128 * 32)     // 1572864 uint2 per layer
#define PREP_TOTAL (PREP_WIH + 3 * WHHP_L)   // 6389760 = 24960*256

__global__ __launch_bounds__(256) void prep_weights(
    const float* __restrict__ wih0, const float* __restrict__ wih1,
    const float* __restrict__ wih2,
    const float* __restrict__ whh0, const float* __restrict__ whh1,
    const float* __restrict__ whh2) {
    long idx = (long)blockIdx.x * 256 + threadIdx.x;
    if (idx < PREP_WIH) {
        const float* src; uint32_t* dst; long off;
        if (idx < WIH_F4_0)                    { src = wih0; dst = g_WIH[0]; off = idx; }
        else if (idx < WIH_F4_0 + WIH_F4_1)    { src = wih1; dst = g_WIH[1]; off = idx - WIH_F4_0; }
        else                                   { src = wih2; dst = g_WIH[2]; off = idx - WIH_F4_0 - WIH_F4_1; }
        uint4 v = *reinterpret_cast<const uint4*>(src + off * 4);
        v.x = f2tf32(v.x); v.y = f2tf32(v.y); v.z = f2tf32(v.z); v.w = f2tf32(v.w);
        *reinterpret_cast<uint4*>(dst + off * 4) = v;
    } else {
        long r = idx - PREP_WIH;
        int l = (int)(r / WHHP_L);
        long r2 = r % WHHP_L;          // = ((((cb*2+ww)*3+g)*128+kf)*32+lane)
        int cb   = (int)(r2 / 24576);  // 0..63
        int r3   = (int)(r2 % 24576);
        int ww   = r3 / 12288;         // 0..1
        int r4   = r3 % 12288;
        int g    = r4 / 4096;
        int r5   = r4 % 4096;
        int kf   = r5 / 32;
        int lane = r5 % 32;
        int gid = lane >> 2, tig = lane & 3;
        const float* whh = (l == 0) ? whh0 : (l == 1) ? whh1 : whh2;
        int row = g * HH + cb * 16 + ww * 8 + gid;
        int col = kf * 8 + tig;
        uint2 v;
        v.x = f2tf32(__float_as_uint(whh[(size_t)row * HH + col]));
        v.y = f2tf32(__float_as_uint(whh[(size_t)row * HH + col + 4]));
        g_WHHP[l][r2] = v;
    }
}

// ---------------------------------------------------------------------------
// tf32 mma GEMM: C[M,N] = A[M,K] @ Wt[N,K]^T + bias[N]   (unchanged)
// ---------------------------------------------------------------------------
#define GP 36
__global__ __launch_bounds__(256) void gemm_mma(const float* __restrict__ A,
                                                const uint32_t* __restrict__ Wt,
                                                const float* __restrict__ bias,
                                                float* __restrict__ C,
                                                int M, int N, int K) {
    __shared__ uint32_t As[128 * GP];
    __shared__ uint32_t Bs[64 * GP];

    int tid = threadIdx.x;
    int warp = tid >> 5, lane = tid & 31;
    int gid = lane >> 2, tig = lane & 3;
    int wm = warp & 3, wn = warp >> 2;
    int rowBase = blockIdx.y * 128;
    int colBase = blockIdx.x * 64;

    int ra[4], ca[4], rb[2], cb2[2];
#pragma unroll
    for (int i = 0; i < 4; i++) { int f4 = tid + i * 256; ra[i] = f4 >> 3; ca[i] = f4 & 7; }
#pragma unroll
    for (int i = 0; i < 2; i++) { int f4 = tid + i * 256; rb[i] = f4 >> 3; cb2[i] = f4 & 7; }

    float acc[2][4][4];
#pragma unroll
    for (int mt = 0; mt < 2; mt++)
#pragma unroll
        for (int nt = 0; nt < 4; nt++)
#pragma unroll
            for (int k = 0; k < 4; k++) acc[mt][nt][k] = 0.f;

    uint4 pa[4], pb[2];
#pragma unroll
    for (int i = 0; i < 4; i++)
        pa[i] = *reinterpret_cast<const uint4*>(&A[(size_t)(rowBase + ra[i]) * K + ca[i] * 4]);
#pragma unroll
    for (int i = 0; i < 2; i++)
        pb[i] = *reinterpret_cast<const uint4*>(&Wt[(size_t)(colBase + rb[i]) * K + cb2[i] * 4]);
#pragma unroll
    for (int i = 0; i < 4; i++) {
        uint4 v = pa[i];
        v.x = f2tf32(v.x); v.y = f2tf32(v.y); v.z = f2tf32(v.z); v.w = f2tf32(v.w);
        *reinterpret_cast<uint4*>(&As[ra[i] * GP + ca[i] * 4]) = v;
    }
#pragma unroll
    for (int i = 0; i < 2; i++)
        *reinterpret_cast<uint4*>(&Bs[rb[i] * GP + cb2[i] * 4]) = pb[i];
    __syncthreads();

    for (int k0 = 0; k0 < K; k0 += 32) {
        bool has_next = (k0 + 32 < K);
        if (has_next) {
#pragma unroll
            for (int i = 0; i < 4; i++)
                pa[i] = *reinterpret_cast<const uint4*>(&A[(size_t)(rowBase + ra[i]) * K + k0 + 32 + ca[i] * 4]);
#pragma unroll
            for (int i = 0; i < 2; i++)
                pb[i] = *reinterpret_cast<const uint4*>(&Wt[(size_t)(colBase + rb[i]) * K + k0 + 32 + cb2[i] * 4]);
        }
#pragma unroll
        for (int ks = 0; ks < 4; ks++) {
            int kk = ks * 8;
            uint32_t a[2][4];
#pragma unroll
            for (int mt = 0; mt < 2; mt++) {
                int r0 = wm * 32 + mt * 16 + gid;
                a[mt][0] = As[r0 * GP + kk + tig];
                a[mt][1] = As[(r0 + 8) * GP + kk + tig];
                a[mt][2] = As[r0 * GP + kk + tig + 4];
                a[mt][3] = As[(r0 + 8) * GP + kk + tig + 4];
            }
#pragma unroll
            for (int nt = 0; nt < 4; nt++) {
                int n0 = wn * 32 + nt * 8 + gid;
                uint32_t b[2] = {Bs[n0 * GP + kk + tig], Bs[n0 * GP + kk + tig + 4]};
#pragma unroll
                for (int mt = 0; mt < 2; mt++) mma_tf32(acc[mt][nt], a[mt], b);
            }
        }
        __syncthreads();
        if (has_next) {
#pragma unroll
            for (int i = 0; i < 4; i++) {
                uint4 v = pa[i];
                v.x = f2tf32(v.x); v.y = f2tf32(v.y); v.z = f2tf32(v.z); v.w = f2tf32(v.w);
                *reinterpret_cast<uint4*>(&As[ra[i] * GP + ca[i] * 4]) = v;
            }
#pragma unroll
            for (int i = 0; i < 2; i++)
                *reinterpret_cast<uint4*>(&Bs[rb[i] * GP + cb2[i] * 4]) = pb[i];
            __syncthreads();
        }
    }

#pragma unroll
    for (int mt = 0; mt < 2; mt++) {
        int row = rowBase + wm * 32 + mt * 16 + gid;
#pragma unroll
        for (int nt = 0; nt < 4; nt++) {
            int col = colBase + wn * 32 + nt * 8 + 2 * tig;
            float2 bi = *reinterpret_cast<const float2*>(&bias[col]);
            float2 v0 = {acc[mt][nt][0] + bi.x, acc[mt][nt][1] + bi.y};
            float2 v1 = {acc[mt][nt][2] + bi.x, acc[mt][nt][3] + bi.y};
            *reinterpret_cast<float2*>(&C[(size_t)row * N + col]) = v0;
            *reinterpret_cast<float2*>(&C[(size_t)(row + 8) * N + col]) = v1;
        }
    }
}

// ---------------------------------------------------------------------------
// Row-group grid barrier: 64 col-blocks per row group
// ---------------------------------------------------------------------------
__device__ __forceinline__ void rowgroup_sync(int rg) {
    __syncthreads();
    if (threadIdx.x == 0) {
        __threadfence();
        volatile unsigned* genp = &g_gen[rg];
        unsigned my = *genp;
        unsigned prev = atomicAdd(&g_cnt[rg], 1u);
        if (prev == NCOLB - 1) {
            atomicExch(&g_cnt[rg], 0u);
            __threadfence();
            *genp = my + 1;
        } else {
            while (*genp == my) { __nanosleep(32); }
        }
    }
    __syncthreads();
}

// ---------------------------------------------------------------------------
// Persistent per-layer GRU kernel, register-only pipeline, L1-FIT PARTITION:
// 128 blocks = 64 col-blocks (16 H-cols each) x 2 rowgroups (64 batch rows).
// Weight slice per block = 3*16*1024*4 = 196 KB < 228 KB L1 -> B-loads become
// L1 hits after warmup. 8 warps: ww=warp&1 owns 8 cols (all gates),
// wm=warp>>1 owns m16 quarter. Per-warp work identical to round 10.
// ---------------------------------------------------------------------------
__global__ __launch_bounds__(256, 1) void gru_layer(const float* __restrict__ XI,   // [T,B,3H]
                                                    const uint2* __restrict__ wP,   // permuted Whh
                                                    const float* __restrict__ bhh,  // [3H]
                                                    float* __restrict__ hseq,       // [T,B,H]
                                                    uint4* __restrict__ hP) {       // [2][32768]
    int tid = threadIdx.x;
    int warp = tid >> 5, lane = tid & 31;
    int gid = lane >> 2, tig = lane & 3;
    int ww = warp & 1;        // n8-column owner (8 cols)
    int wm = warp >> 1;       // m16-quarter owner (0..3)
    int bx = blockIdx.x;
    int cb = bx & 63, rg = bx >> 6;
    int colBase = cb * 16;
    int rowBase = rg * 64;

    // thread-base pointer into permuted weights: offset (g,kf) = (g*128+kf)*32
    const uint2* wPt = wP + ((size_t)(cb * 2 + ww) * 3 * 128) * 32 + lane;

    int col0 = colBase + ww * 8 + 2 * tig;
    float2 ebr = *reinterpret_cast<const float2*>(&bhh[col0]);
    float2 ebz = *reinterpret_cast<const float2*>(&bhh[HH + col0]);
    float2 ebn = *reinterpret_cast<const float2*>(&bhh[2 * HH + col0]);

    int kfg = cb * 2 + ww;                 // this warp's k8-column in hP terms (0..127)

    for (int t = 0; t < TT; t++) {
        const float* hprev = hseq + (size_t)(t - 1) * BB * HH;   // deref only for t>0
        const float* xi_t = XI + (size_t)t * BB * G3;
        float* hout = hseq + (size_t)t * BB * HH;

        float acc[3][4];
#pragma unroll
        for (int g = 0; g < 3; g++)
#pragma unroll
            for (int k = 0; k < 4; k++) acc[g][k] = 0.f;

        if (t > 0) {
            // hP layout per parity: [rg:2][kf:128][mq:4][lane:32] uint4
            const uint4* hPr = hP + ((size_t)((t - 1) & 1)) * 32768
                                 + (size_t)rg * 128 * 4 * 32 + lane;

            auto pref = [&](int c, uint4 (&A)[4], uint2 (&B)[12]) {
#pragma unroll
                for (int ks = 0; ks < 4; ks++)
                    A[ks] = __ldcg(hPr + ((c * 4 + ks) * 4 + wm) * 32);
#pragma unroll
                for (int g = 0; g < 3; g++)
#pragma unroll
                    for (int ks = 0; ks < 4; ks++)
                        B[g * 4 + ks] = __ldg(wPt + (g * 128 + c * 4 + ks) * 32);
            };
            auto comp = [&](const uint4 (&A)[4], const uint2 (&B)[12]) {
#pragma unroll
                for (int ks = 0; ks < 4; ks++) {
                    uint32_t a[4] = {A[ks].x, A[ks].y, A[ks].z, A[ks].w};
#pragma unroll
                    for (int g = 0; g < 3; g++) {
                        uint32_t b[2] = {B[g * 4 + ks].x, B[g * 4 + ks].y};
                        mma_tf32(acc[g], a, b);
                    }
                }
            };

            uint4 A0[4], A1[4];
            uint2 B0[12], B1[12];
            pref(0, A0, B0);
            pref(1, A1, B1);
#pragma unroll 1
            for (int cc = 0; cc < 16; cc++) {
                comp(A0, B0);
                if (cc < 15) pref(2 * cc + 2, A0, B0);
                comp(A1, B1);
                if (cc < 15) pref(2 * cc + 3, A1, B1);
            }
        }

        // Epilogue: this warp's m16 quarter, 8 cols; gate fusion in registers
        {
            uint32_t* hPw = reinterpret_cast<uint32_t*>(hP + ((size_t)(t & 1)) * 32768);
            int base4 = ((rg * 128 + kfg) * 4 + wm) * 32;
#pragma unroll
            for (int kp = 0; kp < 2; kp++) {
                int grow = rowBase + wm * 16 + gid + kp * 8;
                const float* xi = xi_t + (size_t)grow * G3 + col0;
                float2 xr = *reinterpret_cast<const float2*>(xi);
                float2 xz = *reinterpret_cast<const float2*>(xi + HH);
                float2 xn = *reinterpret_cast<const float2*>(xi + 2 * HH);
                float2 hp = {0.f, 0.f};
                if (t > 0)
                    hp = *reinterpret_cast<const float2*>(&hprev[(size_t)grow * HH + col0]);

                float rv0 = acc[0][kp * 2], rv1 = acc[0][kp * 2 + 1];
                float zv0 = acc[1][kp * 2], zv1 = acc[1][kp * 2 + 1];
                float nv0 = acc[2][kp * 2], nv1 = acc[2][kp * 2 + 1];

                float r0 = 1.f / (1.f + __expf(-(xr.x + rv0 + ebr.x)));
                float r1 = 1.f / (1.f + __expf(-(xr.y + rv1 + ebr.y)));
                float z0 = 1.f / (1.f + __expf(-(xz.x + zv0 + ebz.x)));
                float z1 = 1.f / (1.f + __expf(-(xz.y + zv1 + ebz.y)));
                float n0 = tanhf(xn.x + r0 * (nv0 + ebn.x));
                float n1 = tanhf(xn.y + r1 * (nv1 + ebn.y));
                float h0 = (1.f - z0) * n0 + z0 * hp.x;
                float h1 = (1.f - z1) * n1 + z1 * hp.y;

                *reinterpret_cast<float2*>(&hout[(size_t)grow * HH + col0]) =
                    make_float2(h0, h1);

#pragma unroll
                for (int j = 0; j < 2; j++) {
                    int cc2 = 2 * tig + j;
                    int lanep = gid * 4 + (cc2 & 3);
                    int w = (cc2 >> 2) * 2 + kp;
                    uint32_t hv = __float_as_uint(j == 0 ? h0 : h1);
                    hPw[(base4 + lanep) * 4 + w] = f2tf32(hv);
                }
            }
        }

        if (t < TT - 1) rowgroup_sync(rg);
    }
}

// ---------------------------------------------------------------------------
// FC head
// ---------------------------------------------------------------------------
__global__ __launch_bounds__(256) void fc_kernel(const float* __restrict__ last,
                                                 const float* __restrict__ fcw,
                                                 const float* __restrict__ fcb,
                                                 float* __restrict__ out) {
    int warp = (blockIdx.x * blockDim.x + threadIdx.x) >> 5;
    int lane = threadIdx.x & 31;
    if (warp >= BB * PRED) return;
    int b = warp / PRED;
    int p = warp % PRED;
    float s = 0.f;
    const float* lrow = last + (size_t)b * HH;
    const float* wrow = fcw + (size_t)p * HH;
    for (int k = lane; k < HH; k += 32) s += lrow[k] * wrow[k];
#pragma unroll
    for (int off = 16; off; off >>= 1) s += __shfl_xor_sync(0xFFFFFFFFu, s, off);
    if (lane == 0) out[b * PRED + p] = s + fcb[p];
}

// ---------------------------------------------------------------------------
// Launcher
// ---------------------------------------------------------------------------
extern "C" void kernel_launch(void* const* d_in, const int* in_sizes, int n_in,
                              void* d_out, int out_size) {
    const float* x = (const float*)d_in[0];
    const float* w_ih[3] = {(const float*)d_in[1], (const float*)d_in[5], (const float*)d_in[9]};
    const float* w_hh[3] = {(const float*)d_in[2], (const float*)d_in[6], (const float*)d_in[10]};
    const float* b_ih[3] = {(const float*)d_in[3], (const float*)d_in[7], (const float*)d_in[11]};
    const float* b_hh[3] = {(const float*)d_in[4], (const float*)d_in[8], (const float*)d_in[12]};
    const float* fcw = (const float*)d_in[13];
    const float* fcb = (const float*)d_in[14];
    float* out = (float*)d_out;

    float *XT, *XI, *HA, *HB;
    uint32_t* WIH;
    uint2* WHHP;
    uint4* HP;
    cudaGetSymbolAddress((void**)&XT, g_XT);
    cudaGetSymbolAddress((void**)&XI, g_XI);
    cudaGetSymbolAddress((void**)&HA, g_HA);
    cudaGetSymbolAddress((void**)&HB, g_HB);
    cudaGetSymbolAddress((void**)&WIH, g_WIH);
    cudaGetSymbolAddress((void**)&WHHP, g_WHHP);
    cudaGetSymbolAddress((void**)&HP, g_HP);
    const size_t WSTRIDE = (size_t)G3 * HH;

    {
        int total = TT * BB * INDIM;
        transpose_x<<<(total + 255) / 256, 256>>>(x, XT);
    }
    prep_weights<<<PREP_TOTAL / 256, 256>>>(w_ih[0], w_ih[1], w_ih[2],
                                            w_hh[0], w_hh[1], w_hh[2]);

    const float* layin = XT;
    int Kin = INDIM;
    float* seqbuf[3] = {HA, HB, HA};

    for (int l = 0; l < 3; l++) {
        dim3 ggrid(G3 / 64, MROWS / 128);
        gemm_mma<<<ggrid, 256>>>(layin, WIH + (size_t)l * WSTRIDE, b_ih[l], XI, MROWS, G3, Kin);

        gru_layer<<<NCOLB * NROWB, 256>>>(XI, WHHP + (size_t)l * WHHP_L, b_hh[l],
                                          seqbuf[l], HP);

        layin = seqbuf[l];
        Kin = HH;
    }

    {
        const float* last = seqbuf[2] + (size_t)(TT - 1) * BB * HH;
        int warps = BB * PRED;
        int blocks = (warps * 32 + 255) / 256;
        fc_kernel<<<blocks, 256>>>(last, fcw, fcb, out);
    }
}